// round 5
// baseline (speedup 1.0000x reference)
#include <cuda_runtime.h>
#include <math.h>

// Problem constants (fixed shapes per reference)
#define BB 131072
#define DD 64
#define KK 1024
#define DECAYF 0.99f
#define OMDF 0.01f
#define EPSV 1e-5f

// ---------------- scratch (static __device__) ----------------
__device__ float g_znorm[BB];                // max(||z||, eps) per row
__device__ float g_enT[DD * KK];             // normalized embedding, TRANSPOSED [d][k]
__device__ float g_counts[KK];               // segment counts (float)
__device__ float g_dw[KK * DD];              // segment sums of z_n
__device__ float g_embed_unit[KK * DD];      // updated normalized codebook
__device__ int   g_codes[BB];                // argmax codes

// ---------------- helpers ----------------
__device__ __forceinline__ float warpsum(float v) {
#pragma unroll
    for (int o = 16; o; o >>= 1) v += __shfl_xor_sync(0xffffffffu, v, o);
    return v;
}
__device__ __forceinline__ float group16sum(float v) {
#pragma unroll
    for (int o = 8; o; o >>= 1) v += __shfl_xor_sync(0xffffffffu, v, o);
    return v;
}
__device__ __forceinline__ void fma2(unsigned long long& acc,
                                     unsigned long long a, unsigned long long b) {
    asm("fma.rn.f32x2 %0, %1, %2, %0;" : "+l"(acc) : "l"(a), "l"(b));
}
__device__ __forceinline__ void unpack2(unsigned long long v, float& lo, float& hi) {
    asm("mov.b64 {%0, %1}, %2;" : "=f"(lo), "=f"(hi) : "l"(v));
}

// znT smem addressing with XOR swizzle on the 8-row block index.
// element (d, r):  d*128 + ((r>>3) ^ (d & 15))*8 + (r & 7)
__device__ __forceinline__ int znt_idx(int d, int r) {
    return d * 128 + ((((r >> 3) ^ d) & 15) << 3) + (r & 7);
}

// dynamic smem layout (floats):
//   [0, 8192)            znT        (64 d x 128 rows, swizzled)        32 KB
//   [8192, 16384)        enS buf 0  (64 d x 64 cols DUPLICATED pairs)  32 KB
//   [16384, 24576)       enS buf 1                                     32 KB
#define SM_ZNT   0
#define SM_ENS   8192
#define SM_BYTES (24576 * 4)

// ---------------- kernel 1: prep = zero scatter scratch + normalize embedding ----------------
#define ZERO_BLOCKS 260   // ceil((KK*DD + KK) / 256) = 260
__global__ void k_prep(const float* __restrict__ emb) {
    int bid = blockIdx.x;
    if (bid < ZERO_BLOCKS) {
        int idx = bid * 256 + threadIdx.x;
        if (idx < KK * DD) g_dw[idx] = 0.0f;
        else if (idx < KK * DD + KK) g_counts[idx - KK * DD] = 0.0f;
        return;
    }
    // embedding normalize -> transposed layout, warp per row
    int w = (bid - ZERO_BLOCKS) * 8 + (threadIdx.x >> 5);
    int lane = threadIdx.x & 31;
    if (w >= KK) return;
    const float2 v = *(const float2*)(emb + (size_t)w * DD + lane * 2);
    float ss = warpsum(v.x * v.x + v.y * v.y);
    float den = fmaxf(sqrtf(ss), EPSV);
    g_enT[(2 * lane + 0) * KK + w] = v.x / den;
    g_enT[(2 * lane + 1) * KK + w] = v.y / den;
}

// ---------------- kernel 2: fused normalize + sim GEMM (FFMA2) + argmax + scatter ----------------
// CTA: 128 rows x full K (16 chunks of 64 cols). 256 threads = 16 row-groups x 16 col-groups.
// Thread microtile: 8 rows (4 row-PAIRS, packed f32x2) x 4 cols.
// B operands stored pre-duplicated in smem ({b,b} pairs), double-buffered.
__global__ __launch_bounds__(256, 2) void k_sim(const float* __restrict__ ze) {
    extern __shared__ __align__(16) float smem[];
    float* znT = smem + SM_ZNT;

    const int tid = threadIdx.x;
    const int row0 = blockIdx.x * 128;

    // ---- phase 1: load z_e tile, normalize rows (16-lane shfl), transpose into znT ----
#pragma unroll
    for (int i = 0; i < 8; i++) {
        int idx = tid + i * 256;
        int r = idx >> 4, c = idx & 15;
        float4 v = *(const float4*)(ze + (size_t)(row0 + r) * 64 + c * 4);
        float ss = group16sum(v.x * v.x + v.y * v.y + v.z * v.z + v.w * v.w);
        float den = fmaxf(sqrtf(ss), EPSV);
        float inv = 1.0f / den;
        if ((idx & 15) == 0) g_znorm[row0 + r] = den;
        znT[znt_idx(4 * c + 0, r)] = v.x * inv;
        znT[znt_idx(4 * c + 1, r)] = v.y * inv;
        znT[znt_idx(4 * c + 2, r)] = v.z * inv;
        znT[znt_idx(4 * c + 3, r)] = v.w * inv;
    }

    const int rg = tid >> 4, cg = tid & 15;

    // thread's fill slot: idx = tid + i*256 -> d = idx>>4, col quad c4 = (idx&15)*4
    const int fill_d = tid >> 4;          // with +16*i per i
    const int fill_c4 = (tid & 15) * 4;

    float bestv[8];
    int   besti[8];
#pragma unroll
    for (int r = 0; r < 8; r++) { bestv[r] = -1e30f; besti[r] = 0; }

    // prefetch chunk 0, store duplicated into buf0, prefetch chunk 1
    float4 pf[4];
#pragma unroll
    for (int i = 0; i < 4; i++)
        pf[i] = *(const float4*)(g_enT + (fill_d + 16 * i) * KK + fill_c4);
#pragma unroll
    for (int i = 0; i < 4; i++) {
        float* dst = smem + SM_ENS + (fill_d + 16 * i) * 128 + fill_c4 * 2;
        *(float4*)(dst)     = make_float4(pf[i].x, pf[i].x, pf[i].y, pf[i].y);
        *(float4*)(dst + 4) = make_float4(pf[i].z, pf[i].z, pf[i].w, pf[i].w);
    }
#pragma unroll
    for (int i = 0; i < 4; i++)
        pf[i] = *(const float4*)(g_enT + (fill_d + 16 * i) * KK + 64 + fill_c4);

    __syncthreads();   // znT + buf0 ready

    for (int ch = 0; ch < 16; ch++) {
        const float* enB = smem + SM_ENS + (ch & 1) * 8192;

        unsigned long long acc[4][4];
#pragma unroll
        for (int p = 0; p < 4; p++)
#pragma unroll
            for (int j = 0; j < 4; j++) acc[p][j] = 0ULL;

#pragma unroll 4
        for (int d = 0; d < 64; d++) {
            int ai = d * 128 + (((rg ^ d) & 15) << 3);
            ulonglong2 a01 = *(const ulonglong2*)(znT + ai);      // rows 8rg+0..3 (2 pairs)
            ulonglong2 a23 = *(const ulonglong2*)(znT + ai + 4);  // rows 8rg+4..7 (2 pairs)
            ulonglong2 b01 = *(const ulonglong2*)(enB + d * 128 + cg * 8);      // {b0,b0},{b1,b1}
            ulonglong2 b23 = *(const ulonglong2*)(enB + d * 128 + cg * 8 + 4);  // {b2,b2},{b3,b3}
            // consecutive FFMA2s share the B register -> operand-reuse friendly
            fma2(acc[0][0], a01.x, b01.x); fma2(acc[1][0], a01.y, b01.x);
            fma2(acc[2][0], a23.x, b01.x); fma2(acc[3][0], a23.y, b01.x);
            fma2(acc[0][1], a01.x, b01.y); fma2(acc[1][1], a01.y, b01.y);
            fma2(acc[2][1], a23.x, b01.y); fma2(acc[3][1], a23.y, b01.y);
            fma2(acc[0][2], a01.x, b23.x); fma2(acc[1][2], a01.y, b23.x);
            fma2(acc[2][2], a23.x, b23.x); fma2(acc[3][2], a23.y, b23.x);
            fma2(acc[0][3], a01.x, b23.y); fma2(acc[1][3], a01.y, b23.y);
            fma2(acc[2][3], a23.x, b23.y); fma2(acc[3][3], a23.y, b23.y);
        }

        // store prefetched chunk ch+1 into the other buffer; prefetch chunk ch+2
        if (ch < 15) {
            float* dstB = smem + SM_ENS + ((ch + 1) & 1) * 8192;
#pragma unroll
            for (int i = 0; i < 4; i++) {
                float* dst = dstB + (fill_d + 16 * i) * 128 + fill_c4 * 2;
                *(float4*)(dst)     = make_float4(pf[i].x, pf[i].x, pf[i].y, pf[i].y);
                *(float4*)(dst + 4) = make_float4(pf[i].z, pf[i].z, pf[i].w, pf[i].w);
            }
            if (ch < 14) {
#pragma unroll
                for (int i = 0; i < 4; i++)
                    pf[i] = *(const float4*)(g_enT + (fill_d + 16 * i) * KK +
                                             (ch + 2) * 64 + fill_c4);
            }
        }

        // fold into running argmax (col idx ascending within thread -> strict > keeps first)
#pragma unroll
        for (int p = 0; p < 4; p++) {
#pragma unroll
            for (int j = 0; j < 4; j++) {
                float lo, hi;
                unpack2(acc[p][j], lo, hi);
                int idx = ch * 64 + cg * 4 + j;
                if (lo > bestv[2 * p])     { bestv[2 * p]     = lo; besti[2 * p]     = idx; }
                if (hi > bestv[2 * p + 1]) { bestv[2 * p + 1] = hi; besti[2 * p + 1] = idx; }
            }
        }
        __syncthreads();   // next-buffer stores visible; safe to overwrite two-ahead
    }

    // ---- cross-lane argmax: butterfly over the 16 lanes of each row-group ----
    int* codeS = reinterpret_cast<int*>(smem + SM_ENS);   // alias buf0 (all compute done)
#pragma unroll
    for (int r = 0; r < 8; r++) {
        unsigned long long p =
            ((unsigned long long)__float_as_uint(bestv[r]) << 32) | (unsigned)besti[r];
#pragma unroll
        for (int o = 8; o; o >>= 1) {
            unsigned long long q = __shfl_xor_sync(0xffffffffu, p, o);
            float qv = __uint_as_float((unsigned)(q >> 32));
            float pv = __uint_as_float((unsigned)(p >> 32));
            int qi = (int)(unsigned)q, pi = (int)(unsigned)p;
            if (qv > pv || (qv == pv && qi < pi)) p = q;
        }
        if (cg == 0) {
            int code = (int)(unsigned)p;
            int row = 8 * rg + r;
            g_codes[row0 + row] = code;
            codeS[row] = code;
            atomicAdd(&g_counts[code], 1.0f);
        }
    }
    __syncthreads();

    // ---- segment-sum scatter of normalized rows (from znT) into g_dw ----
#pragma unroll
    for (int i = 0; i < 8; i++) {
        int item = tid + i * 256;
        int r = item >> 4, dq = item & 15;
        int code = codeS[r];
#pragma unroll
        for (int j = 0; j < 4; j++) {
            int d = 4 * dq + j;
            atomicAdd(&g_dw[code * 64 + d], znT[znt_idx(d, r)]);
        }
    }
}

// ---------------- kernel 3: EMA update + codebook re-normalize (1 CTA, coalesced) ----------------
__global__ void k_ema(const float* __restrict__ ema_cs, const float* __restrict__ ema_w) {
    __shared__ float sred[1024];
    __shared__ float invden[1024];
    int k = threadIdx.x;
    float cs = ema_cs[k] * DECAYF + g_counts[k] * OMDF;
    sred[k] = cs;
    __syncthreads();
    for (int s = 512; s > 0; s >>= 1) {
        if (k < s) sred[k] += sred[k + s];
        __syncthreads();
    }
    float n = sred[0];
    float cluster = (cs + EPSV) / (n + KK * EPSV) * n;
    invden[k] = 1.0f / fmaxf(cluster, EPSV);
    __syncthreads();

    int lane = k & 15;
#pragma unroll 1
    for (int g = 0; g < 16; g++) {
        int k2 = (g << 6) + (k >> 4);
        float inv = invden[k2];
        float4 w = *(const float4*)(ema_w + k2 * 64 + lane * 4);
        float4 dv = *(const float4*)(g_dw + k2 * 64 + lane * 4);
        float4 m;
        m.x = (w.x * DECAYF + dv.x * OMDF) * inv;
        m.y = (w.y * DECAYF + dv.y * OMDF) * inv;
        m.z = (w.z * DECAYF + dv.z * OMDF) * inv;
        m.w = (w.w * DECAYF + dv.w * OMDF) * inv;
        float ss = group16sum(m.x * m.x + m.y * m.y + m.z * m.z + m.w * m.w);
        float ni = 1.0f / fmaxf(sqrtf(ss), EPSV);
        float4 o = make_float4(m.x * ni, m.y * ni, m.z * ni, m.w * ni);
        *(float4*)(g_embed_unit + k2 * 64 + lane * 4) = o;
    }
}

// ---------------- kernel 4: gather + outputs (warp per row) ----------------
__global__ void k_out(const float* __restrict__ ze, float* __restrict__ out, int write_aux) {
    int w = (blockIdx.x * blockDim.x + threadIdx.x) >> 5;
    int lane = threadIdx.x & 31;
    if (w >= BB) return;
    int c = g_codes[w];
    float zl = g_znorm[w];
    float zinv = 1.0f / zl;
    float2 e = *(const float2*)(g_embed_unit + c * 64 + lane * 2);
    float ss = warpsum(e.x * e.x + e.y * e.y);
    float ed = fmaxf(sqrtf(ss), EPSV);
    float2 en = make_float2(e.x / ed, e.y / ed);
    float2 zev = *(const float2*)(ze + (size_t)w * 64 + lane * 2);
    float2 zn = make_float2(zev.x * zinv, zev.y * zinv);
    float dot = warpsum(zn.x * en.x + zn.y * en.y);
    float2 zq = make_float2(e.x * zl, e.y * zl);
    float2 o = make_float2(zev.x + (zq.x - zev.x), zev.y + (zq.y - zev.y));
    *(float2*)(out + (size_t)w * 64 + lane * 2) = o;
    if (write_aux && lane == 0) {
        out[(size_t)BB * DD + w] = (float)c;          // codes (numeric cast)
        out[(size_t)BB * DD + BB + w] = 1.0f - dot;   // dists
    }
}

// ---------------- launcher ----------------
extern "C" void kernel_launch(void* const* d_in, const int* in_sizes, int n_in,
                              void* d_out, int out_size) {
    const float* ze  = (const float*)d_in[0];   // z_e           [B, 64]
    const float* emb = (const float*)d_in[1];   // embedding     [K, 64]
    const float* ecs = (const float*)d_in[2];   // ema_cluster   [K]
    const float* ew  = (const float*)d_in[3];   // ema_w         [K, 64]
    float* out = (float*)d_out;

    long long need = (long long)BB * DD + 2LL * BB;
    int write_aux = ((long long)out_size >= need) ? 1 : 0;

    // idempotent, host-state only (legal under graph capture; not an allocation)
    cudaFuncSetAttribute(k_sim, cudaFuncAttributeMaxDynamicSharedMemorySize, SM_BYTES);

    k_prep<<<ZERO_BLOCKS + KK / 8, 256>>>(emb);
    k_sim<<<BB / 128, 256, SM_BYTES>>>(ze);
    k_ema<<<1, 1024>>>(ecs, ew);
    k_out<<<BB / 8, 256>>>(ze, out, write_aux);
}

// round 7
// speedup vs baseline: 1.8357x; 1.8357x over previous
#include <cuda_runtime.h>
#include <cuda_bf16.h>
#include <math.h>
#include <stdint.h>

// Problem constants
#define BB 131072
#define DD 64
#define KK 1024
#define DECAYF 0.99f
#define OMDF 0.01f
#define EPSV 1e-5f

// ---------------- scratch ----------------
__device__ float    g_en[KK * DD];        // normalized embedding fp32 (for exact rescore)
__device__ unsigned g_ebf[KK * 96];       // B rows bf16x2 pairs: [0:32)=hi, [32:64)=hi, [64:96)=lo
__device__ float    g_counts[KK];
__device__ float    g_dw[KK * DD];
__device__ float    g_embed_unit[KK * DD];
__device__ float    g_znorm[BB];
__device__ int      g_codes[BB];
__device__ int      g_t1[BB];
__device__ int      g_t2[BB];

// ---------------- helpers ----------------
__device__ __forceinline__ float warpsum(float v) {
#pragma unroll
    for (int o = 16; o; o >>= 1) v += __shfl_xor_sync(0xffffffffu, v, o);
    return v;
}
__device__ __forceinline__ float group16sum(float v) {
#pragma unroll
    for (int o = 8; o; o >>= 1) v += __shfl_xor_sync(0xffffffffu, v, o);
    return v;
}
__device__ __forceinline__ uint32_t smem_u32(const void* p) {
    uint32_t a;
    asm("{ .reg .u64 t; cvta.to.shared.u64 t, %1; cvt.u32.u64 %0, t; }" : "=r"(a) : "l"(p));
    return a;
}
// top-2 insert with tie -> lower index (preserves first-occurrence argmax semantics)
__device__ __forceinline__ void ins(float v, int i, float& v1, int& i1, float& v2, int& i2) {
    bool b1 = (v > v1) || (v == v1 && i < i1);
    bool b2 = (v > v2) || (v == v2 && i < i2);
    if (b1) { v2 = v1; i2 = i1; v1 = v; i1 = i; }
    else if (b2) { v2 = v; i2 = i; }
}

// ---------------- kernel 1: prep = zero scratch + normalize embedding (fp32 + bf16 split) ----------------
#define ZERO_BLOCKS 260
__global__ void k_prep(const float* __restrict__ emb) {
    int bid = blockIdx.x;
    if (bid < ZERO_BLOCKS) {
        int idx = bid * 256 + threadIdx.x;
        if (idx < KK * DD) g_dw[idx] = 0.0f;
        else if (idx < KK * DD + KK) g_counts[idx - KK * DD] = 0.0f;
        return;
    }
    int w = (bid - ZERO_BLOCKS) * 8 + (threadIdx.x >> 5);
    int lane = threadIdx.x & 31;
    if (w >= KK) return;
    float2 v = *(const float2*)(emb + (size_t)w * DD + lane * 2);
    float ss = warpsum(v.x * v.x + v.y * v.y);
    float inv = 1.0f / fmaxf(sqrtf(ss), EPSV);
    float e0 = v.x * inv, e1 = v.y * inv;
    *(float2*)(g_en + (size_t)w * DD + lane * 2) = make_float2(e0, e1);
    __nv_bfloat16 h0 = __float2bfloat16(e0), h1 = __float2bfloat16(e1);
    float l0 = e0 - __bfloat162float(h0), l1 = e1 - __bfloat162float(h1);
    __nv_bfloat16 q0 = __float2bfloat16(l0), q1 = __float2bfloat16(l1);
    unsigned uh = ((unsigned)__bfloat16_as_ushort(h1) << 16) | __bfloat16_as_ushort(h0);
    unsigned ul = ((unsigned)__bfloat16_as_ushort(q1) << 16) | __bfloat16_as_ushort(q0);
    g_ebf[w * 96 + lane]      = uh;
    g_ebf[w * 96 + 32 + lane] = uh;
    g_ebf[w * 96 + 64 + lane] = ul;
}

// ---------------- kernel 2: mma.sync bf16 split GEMM + per-row top-2 ----------------
// smem: one buffer [128 rows][200 bf16] (row stride 100 u32 = 400 B -> 4-bank shift, conflict-free).
// Phase A: z tile (normalized, split) -> ldmatrix into 48 regs/warp. Then 8 chunks of 128 codes.
#define ROWU32 100
#define SMEM_BYTES (128 * 400)

__global__ __launch_bounds__(256, 2) void k_sim(const float* __restrict__ ze) {
    extern __shared__ __align__(16) unsigned sB[];
    const int tid = threadIdx.x, wid = tid >> 5, lane = tid & 31;
    const int row0 = blockIdx.x * 128;
    const uint32_t sbase = smem_u32(sB);

    // ---- phase A: normalize z rows, split hi/lo, store [row][k-pairs] ----
#pragma unroll 1
    for (int it = 0; it < 16; it++) {
        int r = wid + it * 8;
        float2 v = *(const float2*)(ze + (size_t)(row0 + r) * 64 + lane * 2);
        float ss = warpsum(v.x * v.x + v.y * v.y);
        float den = fmaxf(sqrtf(ss), EPSV);
        float inv = 1.0f / den;
        if (lane == 0) g_znorm[row0 + r] = den;
        float z0 = v.x * inv, z1 = v.y * inv;
        __nv_bfloat16 h0 = __float2bfloat16(z0), h1 = __float2bfloat16(z1);
        float l0 = z0 - __bfloat162float(h0), l1 = z1 - __bfloat162float(h1);
        __nv_bfloat16 q0 = __float2bfloat16(l0), q1 = __float2bfloat16(l1);
        unsigned uh = ((unsigned)__bfloat16_as_ushort(h1) << 16) | __bfloat16_as_ushort(h0);
        unsigned ul = ((unsigned)__bfloat16_as_ushort(q1) << 16) | __bfloat16_as_ushort(q0);
        sB[r * ROWU32 + lane]      = uh;   // k[0:64)   = z_hi
        sB[r * ROWU32 + 32 + lane] = ul;   // k[64:128) = z_lo
        sB[r * ROWU32 + 64 + lane] = uh;   // k[128:192)= z_hi
    }
    __syncthreads();

    // ---- A fragments: warp owns rows m0..m0+15, all 12 k16-steps, kept in regs ----
    const int m0 = wid * 16;
    uint32_t af[12][4];
    {
        // thread t: row = m0 + (t&15), col(bf16) = ks*16 + (t>>4)*8
        uint32_t aaddr = sbase + (uint32_t)(m0 + (lane & 15)) * 400 + ((lane >> 4) << 4);
#pragma unroll
        for (int ks = 0; ks < 12; ks++) {
            asm volatile("ldmatrix.sync.aligned.m8n8.x4.shared.b16 {%0,%1,%2,%3}, [%4];"
                : "=r"(af[ks][0]), "=r"(af[ks][1]), "=r"(af[ks][2]), "=r"(af[ks][3])
                : "r"(aaddr + ks * 32));
        }
    }
    __syncthreads();   // done reading A region -> reuse buffer for B

    // top-2 state: rows (m0 + lane/4) and (m0 + lane/4 + 8)
    float va1 = -1e30f, va2 = -1e30f; int ia1 = 0, ia2 = 0;
    float vb1 = -1e30f, vb2 = -1e30f; int ib1 = 0, ib2 = 0;

#pragma unroll 1
    for (int c = 0; c < 8; c++) {
        // fill B chunk: codes c*128 .. c*128+127, as [n][k-pairs]
#pragma unroll
        for (int i = 0; i < 48; i++) {
            int idx = i * 256 + tid;
            int n = idx / 96, p = idx - n * 96;
            sB[n * ROWU32 + p] = g_ebf[(size_t)(c * 128 + n) * 96 + p];
        }
        __syncthreads();

#pragma unroll 1
        for (int np = 0; np < 8; np++) {
            const int n0 = np * 16;
            float c0[4] = {0.f, 0.f, 0.f, 0.f};
            float c1[4] = {0.f, 0.f, 0.f, 0.f};
            // thread t: row = n0 + ((t>>4)<<3) + (t&7), col(bf16) = ks*16 + (t&8)
            uint32_t baddr = sbase + (uint32_t)(n0 + ((lane >> 4) << 3) + (lane & 7)) * 400 +
                             ((lane & 8) << 1);
#pragma unroll
            for (int ks = 0; ks < 12; ks++) {
                uint32_t b0, b1, b2, b3;
                asm volatile("ldmatrix.sync.aligned.m8n8.x4.shared.b16 {%0,%1,%2,%3}, [%4];"
                    : "=r"(b0), "=r"(b1), "=r"(b2), "=r"(b3) : "r"(baddr + ks * 32));
                asm volatile(
                    "mma.sync.aligned.m16n8k16.row.col.f32.bf16.bf16.f32 "
                    "{%0,%1,%2,%3}, {%4,%5,%6,%7}, {%8,%9}, {%0,%1,%2,%3};"
                    : "+f"(c0[0]), "+f"(c0[1]), "+f"(c0[2]), "+f"(c0[3])
                    : "r"(af[ks][0]), "r"(af[ks][1]), "r"(af[ks][2]), "r"(af[ks][3]),
                      "r"(b0), "r"(b1));
                asm volatile(
                    "mma.sync.aligned.m16n8k16.row.col.f32.bf16.bf16.f32 "
                    "{%0,%1,%2,%3}, {%4,%5,%6,%7}, {%8,%9}, {%0,%1,%2,%3};"
                    : "+f"(c1[0]), "+f"(c1[1]), "+f"(c1[2]), "+f"(c1[3])
                    : "r"(af[ks][0]), "r"(af[ks][1]), "r"(af[ks][2]), "r"(af[ks][3]),
                      "r"(b2), "r"(b3));
            }
            // C mapping: c[0],c[1] -> (row lane/4,   col 2*(lane&3)+{0,1})
            //            c[2],c[3] -> (row lane/4+8, col 2*(lane&3)+{0,1})
            int colb = c * 128 + n0 + 2 * (lane & 3);
            ins(c0[0], colb,     va1, ia1, va2, ia2);
            ins(c0[1], colb + 1, va1, ia1, va2, ia2);
            ins(c0[2], colb,     vb1, ib1, vb2, ib2);
            ins(c0[3], colb + 1, vb1, ib1, vb2, ib2);
            ins(c1[0], colb + 8, va1, ia1, va2, ia2);
            ins(c1[1], colb + 9, va1, ia1, va2, ia2);
            ins(c1[2], colb + 8, vb1, ib1, vb2, ib2);
            ins(c1[3], colb + 9, vb1, ib1, vb2, ib2);
        }
        __syncthreads();
    }

    // ---- merge top-2 across the 4 threads of each quad (disjoint col sets) ----
#pragma unroll
    for (int o = 1; o <= 2; o <<= 1) {
        float w1 = __shfl_xor_sync(0xffffffffu, va1, o);
        int   j1 = __shfl_xor_sync(0xffffffffu, ia1, o);
        float w2 = __shfl_xor_sync(0xffffffffu, va2, o);
        int   j2 = __shfl_xor_sync(0xffffffffu, ia2, o);
        ins(w1, j1, va1, ia1, va2, ia2);
        ins(w2, j2, va1, ia1, va2, ia2);
        float x1 = __shfl_xor_sync(0xffffffffu, vb1, o);
        int   k1 = __shfl_xor_sync(0xffffffffu, ib1, o);
        float x2 = __shfl_xor_sync(0xffffffffu, vb2, o);
        int   k2 = __shfl_xor_sync(0xffffffffu, ib2, o);
        ins(x1, k1, vb1, ib1, vb2, ib2);
        ins(x2, k2, vb1, ib1, vb2, ib2);
    }
    if ((lane & 3) == 0) {
        int ra = row0 + m0 + (lane >> 2);
        g_t1[ra]     = ia1; g_t2[ra]     = ia2;
        g_t1[ra + 8] = ib1; g_t2[ra + 8] = ib2;
    }
}

// ---------------- kernel 3: exact fp32 rescore + scatter ----------------
__global__ void k_rescore(const float* __restrict__ ze) {
    int w = (blockIdx.x * blockDim.x + threadIdx.x) >> 5;
    int lane = threadIdx.x & 31;
    if (w >= BB) return;
    float2 v = *(const float2*)(ze + (size_t)w * 64 + lane * 2);
    float ss = warpsum(v.x * v.x + v.y * v.y);
    float den = fmaxf(sqrtf(ss), EPSV);
    float inv = 1.0f / den;
    float zn0 = v.x * inv, zn1 = v.y * inv;
    int i1 = g_t1[w], i2 = g_t2[w];
    float2 e1 = *(const float2*)(g_en + (size_t)i1 * 64 + lane * 2);
    float2 e2 = *(const float2*)(g_en + (size_t)i2 * 64 + lane * 2);
    float d1 = warpsum(zn0 * e1.x + zn1 * e1.y);
    float d2 = warpsum(zn0 * e2.x + zn1 * e2.y);
    int code;
    if (d1 > d2) code = i1;
    else if (d2 > d1) code = i2;
    else code = min(i1, i2);
    if (lane == 0) {
        g_codes[w] = code;
        atomicAdd(&g_counts[code], 1.0f);
    }
    atomicAdd(&g_dw[code * 64 + 2 * lane],     zn0);
    atomicAdd(&g_dw[code * 64 + 2 * lane + 1], zn1);
}

// ---------------- kernel 4: EMA + codebook re-normalize ----------------
__global__ void k_ema(const float* __restrict__ ema_cs, const float* __restrict__ ema_w) {
    __shared__ float sred[1024];
    __shared__ float invden[1024];
    int k = threadIdx.x;
    float cs = ema_cs[k] * DECAYF + g_counts[k] * OMDF;
    sred[k] = cs;
    __syncthreads();
    for (int s = 512; s > 0; s >>= 1) {
        if (k < s) sred[k] += sred[k + s];
        __syncthreads();
    }
    float n = sred[0];
    float cluster = (cs + EPSV) / (n + KK * EPSV) * n;
    invden[k] = 1.0f / fmaxf(cluster, EPSV);
    __syncthreads();
    int lane = k & 15;
#pragma unroll 1
    for (int g = 0; g < 16; g++) {
        int k2 = (g << 6) + (k >> 4);
        float inv = invden[k2];
        float4 w = *(const float4*)(ema_w + k2 * 64 + lane * 4);
        float4 dv = *(const float4*)(g_dw + k2 * 64 + lane * 4);
        float4 m;
        m.x = (w.x * DECAYF + dv.x * OMDF) * inv;
        m.y = (w.y * DECAYF + dv.y * OMDF) * inv;
        m.z = (w.z * DECAYF + dv.z * OMDF) * inv;
        m.w = (w.w * DECAYF + dv.w * OMDF) * inv;
        float ss = group16sum(m.x * m.x + m.y * m.y + m.z * m.z + m.w * m.w);
        float ni = 1.0f / fmaxf(sqrtf(ss), EPSV);
        *(float4*)(g_embed_unit + k2 * 64 + lane * 4) =
            make_float4(m.x * ni, m.y * ni, m.z * ni, m.w * ni);
    }
}

// ---------------- kernel 5: gather + outputs ----------------
__global__ void k_out(const float* __restrict__ ze, float* __restrict__ out, int write_aux) {
    int w = (blockIdx.x * blockDim.x + threadIdx.x) >> 5;
    int lane = threadIdx.x & 31;
    if (w >= BB) return;
    int c = g_codes[w];
    float zl = g_znorm[w];
    float zinv = 1.0f / zl;
    float2 e = *(const float2*)(g_embed_unit + (size_t)c * 64 + lane * 2);
    float ss = warpsum(e.x * e.x + e.y * e.y);
    float ed = fmaxf(sqrtf(ss), EPSV);
    float2 en = make_float2(e.x / ed, e.y / ed);
    float2 zev = *(const float2*)(ze + (size_t)w * 64 + lane * 2);
    float2 zn = make_float2(zev.x * zinv, zev.y * zinv);
    float dot = warpsum(zn.x * en.x + zn.y * en.y);
    float2 zq = make_float2(e.x * zl, e.y * zl);
    float2 o = make_float2(zev.x + (zq.x - zev.x), zev.y + (zq.y - zev.y));
    *(float2*)(out + (size_t)w * 64 + lane * 2) = o;
    if (write_aux && lane == 0) {
        out[(size_t)BB * DD + w] = (float)c;
        out[(size_t)BB * DD + BB + w] = 1.0f - dot;
    }
}

// ---------------- launcher ----------------
extern "C" void kernel_launch(void* const* d_in, const int* in_sizes, int n_in,
                              void* d_out, int out_size) {
    const float* ze  = (const float*)d_in[0];
    const float* emb = (const float*)d_in[1];
    const float* ecs = (const float*)d_in[2];
    const float* ew  = (const float*)d_in[3];
    float* out = (float*)d_out;

    long long need = (long long)BB * DD + 2LL * BB;
    int write_aux = ((long long)out_size >= need) ? 1 : 0;

    cudaFuncSetAttribute(k_sim, cudaFuncAttributeMaxDynamicSharedMemorySize, SMEM_BYTES);

    k_prep<<<ZERO_BLOCKS + KK / 8, 256>>>(emb);
    k_sim<<<BB / 128, 256, SMEM_BYTES>>>(ze);
    k_rescore<<<BB / 8, 256>>>(ze);
    k_ema<<<1, 1024>>>(ecs, ew);
    k_out<<<BB / 8, 256>>>(ze, out, write_aux);
}

// round 9
// speedup vs baseline: 1.8575x; 1.0119x over previous
#include <cuda_runtime.h>
#include <cuda_bf16.h>
#include <math.h>
#include <stdint.h>

// Problem constants
#define BB 131072
#define DD 64
#define KK 1024
#define DECAYF 0.99f
#define OMDF 0.01f
#define EPSV 1e-5f

// ---------------- scratch ----------------
__device__ float    g_en[KK * DD];        // normalized embedding fp32 (for exact rescore)
__device__ unsigned g_ebf[KK * 96];       // B rows bf16x2 pairs: [0:32)=hi, [32:64)=hi, [64:96)=lo
__device__ float    g_counts[KK];
__device__ float    g_dw[KK * DD];
__device__ float    g_embed_unit[KK * DD];
__device__ float    g_znorm[BB];
__device__ int      g_codes[BB];
__device__ int      g_t1[BB];
__device__ int      g_t2[BB];

// ---------------- helpers ----------------
__device__ __forceinline__ float warpsum(float v) {
#pragma unroll
    for (int o = 16; o; o >>= 1) v += __shfl_xor_sync(0xffffffffu, v, o);
    return v;
}
__device__ __forceinline__ float group16sum(float v) {
#pragma unroll
    for (int o = 8; o; o >>= 1) v += __shfl_xor_sync(0xffffffffu, v, o);
    return v;
}
__device__ __forceinline__ uint32_t smem_u32(const void* p) {
    uint32_t a;
    asm("{ .reg .u64 t; cvta.to.shared.u64 t, %1; cvt.u32.u64 %0, t; }" : "=r"(a) : "l"(p));
    return a;
}
// top-2 insert with tie -> lower index (preserves first-occurrence argmax semantics)
__device__ __forceinline__ void ins(float v, int i, float& v1, int& i1, float& v2, int& i2) {
    bool b1 = (v > v1) || (v == v1 && i < i1);
    bool b2 = (v > v2) || (v == v2 && i < i2);
    if (b1) { v2 = v1; i2 = i1; v1 = v; i1 = i; }
    else if (b2) { v2 = v; i2 = i; }
}
#define LDSM4(r0, r1, r2, r3, addr) \
    asm volatile("ldmatrix.sync.aligned.m8n8.x4.shared.b16 {%0,%1,%2,%3}, [%4];" \
        : "=r"(r0), "=r"(r1), "=r"(r2), "=r"(r3) : "r"(addr))
#define MMA16816(c, a, b0, b1) \
    asm volatile("mma.sync.aligned.m16n8k16.row.col.f32.bf16.bf16.f32 " \
        "{%0,%1,%2,%3}, {%4,%5,%6,%7}, {%8,%9}, {%0,%1,%2,%3};" \
        : "+f"((c)[0]), "+f"((c)[1]), "+f"((c)[2]), "+f"((c)[3]) \
        : "r"((a)[0]), "r"((a)[1]), "r"((a)[2]), "r"((a)[3]), "r"(b0), "r"(b1))

// ---------------- kernel 1: prep = zero scratch + normalize embedding (fp32 + bf16 split) ----------------
#define ZERO_BLOCKS 260
__global__ void k_prep(const float* __restrict__ emb) {
    int bid = blockIdx.x;
    if (bid < ZERO_BLOCKS) {
        int idx = bid * 256 + threadIdx.x;
        if (idx < KK * DD) g_dw[idx] = 0.0f;
        else if (idx < KK * DD + KK) g_counts[idx - KK * DD] = 0.0f;
        return;
    }
    int w = (bid - ZERO_BLOCKS) * 8 + (threadIdx.x >> 5);
    int lane = threadIdx.x & 31;
    if (w >= KK) return;
    float2 v = *(const float2*)(emb + (size_t)w * DD + lane * 2);
    float ss = warpsum(v.x * v.x + v.y * v.y);
    float inv = 1.0f / fmaxf(sqrtf(ss), EPSV);
    float e0 = v.x * inv, e1 = v.y * inv;
    *(float2*)(g_en + (size_t)w * DD + lane * 2) = make_float2(e0, e1);
    __nv_bfloat16 h0 = __float2bfloat16(e0), h1 = __float2bfloat16(e1);
    float l0 = e0 - __bfloat162float(h0), l1 = e1 - __bfloat162float(h1);
    __nv_bfloat16 q0 = __float2bfloat16(l0), q1 = __float2bfloat16(l1);
    unsigned uh = ((unsigned)__bfloat16_as_ushort(h1) << 16) | __bfloat16_as_ushort(h0);
    unsigned ul = ((unsigned)__bfloat16_as_ushort(q1) << 16) | __bfloat16_as_ushort(q0);
    g_ebf[w * 96 + lane]      = uh;
    g_ebf[w * 96 + 32 + lane] = uh;
    g_ebf[w * 96 + 64 + lane] = ul;
}

// ---------------- kernel 2: mma.sync bf16 split GEMM + per-row top-2 ----------------
#define ROWU32 100
#define SMEM_BYTES (128 * 400)

__global__ __launch_bounds__(256, 2) void k_sim(const float* __restrict__ ze) {
    extern __shared__ __align__(16) unsigned sB[];
    const int tid = threadIdx.x, wid = tid >> 5, lane = tid & 31;
    const int row0 = blockIdx.x * 128;
    const uint32_t sbase = smem_u32(sB);

    // ---- phase A: normalize z rows, split hi/lo, store [row][k-pairs] ----
#pragma unroll 1
    for (int it = 0; it < 16; it++) {
        int r = wid + it * 8;
        float2 v = *(const float2*)(ze + (size_t)(row0 + r) * 64 + lane * 2);
        float ss = warpsum(v.x * v.x + v.y * v.y);
        float den = fmaxf(sqrtf(ss), EPSV);
        float inv = 1.0f / den;
        if (lane == 0) g_znorm[row0 + r] = den;
        float z0 = v.x * inv, z1 = v.y * inv;
        __nv_bfloat16 h0 = __float2bfloat16(z0), h1 = __float2bfloat16(z1);
        float l0 = z0 - __bfloat162float(h0), l1 = z1 - __bfloat162float(h1);
        __nv_bfloat16 q0 = __float2bfloat16(l0), q1 = __float2bfloat16(l1);
        unsigned uh = ((unsigned)__bfloat16_as_ushort(h1) << 16) | __bfloat16_as_ushort(h0);
        unsigned ul = ((unsigned)__bfloat16_as_ushort(q1) << 16) | __bfloat16_as_ushort(q0);
        sB[r * ROWU32 + lane]      = uh;   // k[0:64)   = z_hi
        sB[r * ROWU32 + 32 + lane] = ul;   // k[64:128) = z_lo
        sB[r * ROWU32 + 64 + lane] = uh;   // k[128:192)= z_hi
    }
    __syncthreads();

    // ---- A fragments: warp owns rows m0..m0+15, all 12 k16-steps, kept in regs ----
    const int m0 = wid * 16;
    uint32_t af[12][4];
    {
        uint32_t aaddr = sbase + (uint32_t)(m0 + (lane & 15)) * 400 + ((lane >> 4) << 4);
#pragma unroll
        for (int ks = 0; ks < 12; ks++)
            LDSM4(af[ks][0], af[ks][1], af[ks][2], af[ks][3], aaddr + ks * 32);
    }
    __syncthreads();   // done reading A region -> reuse buffer for B

    float va1 = -1e30f, va2 = -1e30f; int ia1 = 0, ia2 = 0;
    float vb1 = -1e30f, vb2 = -1e30f; int ib1 = 0, ib2 = 0;

#pragma unroll 1
    for (int c = 0; c < 8; c++) {
#pragma unroll
        for (int i = 0; i < 48; i++) {
            int idx = i * 256 + tid;
            int n = idx / 96, p = idx - n * 96;
            sB[n * ROWU32 + p] = g_ebf[(size_t)(c * 128 + n) * 96 + p];
        }
        __syncthreads();

#pragma unroll 1
        for (int np = 0; np < 8; np++) {
            const int n0 = np * 16;
            // 4 independent accumulator chains (ks parity x n8-half)
            float c0a[4] = {0,0,0,0}, c0b[4] = {0,0,0,0};
            float c1a[4] = {0,0,0,0}, c1b[4] = {0,0,0,0};
            uint32_t baddr = sbase + (uint32_t)(n0 + ((lane >> 4) << 3) + (lane & 7)) * 400 +
                             ((lane & 8) << 1);
            uint32_t bb[2][4];
            LDSM4(bb[0][0], bb[0][1], bb[0][2], bb[0][3], baddr);
#pragma unroll
            for (int ks = 0; ks < 12; ks++) {
                if (ks < 11)
                    LDSM4(bb[(ks + 1) & 1][0], bb[(ks + 1) & 1][1],
                          bb[(ks + 1) & 1][2], bb[(ks + 1) & 1][3], baddr + (ks + 1) * 32);
                uint32_t* b = bb[ks & 1];
                if (ks & 1) {
                    MMA16816(c0b, af[ks], b[0], b[1]);
                    MMA16816(c1b, af[ks], b[2], b[3]);
                } else {
                    MMA16816(c0a, af[ks], b[0], b[1]);
                    MMA16816(c1a, af[ks], b[2], b[3]);
                }
            }
            float c0[4], c1[4];
#pragma unroll
            for (int j = 0; j < 4; j++) { c0[j] = c0a[j] + c0b[j]; c1[j] = c1a[j] + c1b[j]; }

            int colb = c * 128 + n0 + 2 * (lane & 3);
            // guarded top-2 fold: full insert only if group max can enter top-2
            float mxa = fmaxf(fmaxf(c0[0], c0[1]), fmaxf(c1[0], c1[1]));
            if (mxa >= va2) {
                ins(c0[0], colb,     va1, ia1, va2, ia2);
                ins(c0[1], colb + 1, va1, ia1, va2, ia2);
                ins(c1[0], colb + 8, va1, ia1, va2, ia2);
                ins(c1[1], colb + 9, va1, ia1, va2, ia2);
            }
            float mxb = fmaxf(fmaxf(c0[2], c0[3]), fmaxf(c1[2], c1[3]));
            if (mxb >= vb2) {
                ins(c0[2], colb,     vb1, ib1, vb2, ib2);
                ins(c0[3], colb + 1, vb1, ib1, vb2, ib2);
                ins(c1[2], colb + 8, vb1, ib1, vb2, ib2);
                ins(c1[3], colb + 9, vb1, ib1, vb2, ib2);
            }
        }
        __syncthreads();
    }

    // ---- merge top-2 across the 4 threads of each quad (disjoint col sets) ----
#pragma unroll
    for (int o = 1; o <= 2; o <<= 1) {
        float w1 = __shfl_xor_sync(0xffffffffu, va1, o);
        int   j1 = __shfl_xor_sync(0xffffffffu, ia1, o);
        float w2 = __shfl_xor_sync(0xffffffffu, va2, o);
        int   j2 = __shfl_xor_sync(0xffffffffu, ia2, o);
        ins(w1, j1, va1, ia1, va2, ia2);
        ins(w2, j2, va1, ia1, va2, ia2);
        float x1 = __shfl_xor_sync(0xffffffffu, vb1, o);
        int   k1 = __shfl_xor_sync(0xffffffffu, ib1, o);
        float x2 = __shfl_xor_sync(0xffffffffu, vb2, o);
        int   k2 = __shfl_xor_sync(0xffffffffu, ib2, o);
        ins(x1, k1, vb1, ib1, vb2, ib2);
        ins(x2, k2, vb1, ib1, vb2, ib2);
    }
    if ((lane & 3) == 0) {
        int ra = row0 + m0 + (lane >> 2);
        g_t1[ra]     = ia1; g_t2[ra]     = ia2;
        g_t1[ra + 8] = ib1; g_t2[ra + 8] = ib2;
    }
}

// ---------------- kernel 3: exact fp32 rescore + scatter ----------------
__global__ void k_rescore(const float* __restrict__ ze) {
    int w = (blockIdx.x * blockDim.x + threadIdx.x) >> 5;
    int lane = threadIdx.x & 31;
    if (w >= BB) return;
    float2 v = *(const float2*)(ze + (size_t)w * 64 + lane * 2);
    float ss = warpsum(v.x * v.x + v.y * v.y);
    float den = fmaxf(sqrtf(ss), EPSV);
    float inv = 1.0f / den;
    float zn0 = v.x * inv, zn1 = v.y * inv;
    int i1 = g_t1[w], i2 = g_t2[w];
    float2 e1 = *(const float2*)(g_en + (size_t)i1 * 64 + lane * 2);
    float2 e2 = *(const float2*)(g_en + (size_t)i2 * 64 + lane * 2);
    float d1 = warpsum(zn0 * e1.x + zn1 * e1.y);
    float d2 = warpsum(zn0 * e2.x + zn1 * e2.y);
    int code;
    if (d1 > d2) code = i1;
    else if (d2 > d1) code = i2;
    else code = min(i1, i2);
    if (lane == 0) {
        g_codes[w] = code;
        atomicAdd(&g_counts[code], 1.0f);
    }
    atomicAdd(&g_dw[code * 64 + 2 * lane],     zn0);
    atomicAdd(&g_dw[code * 64 + 2 * lane + 1], zn1);
}

// ---------------- kernel 4: EMA + codebook re-normalize (16 CTAs) ----------------
__global__ void k_ema(const float* __restrict__ ema_cs, const float* __restrict__ ema_w) {
    __shared__ float sred[256];
    int tid = threadIdx.x;
    // every CTA redundantly computes n = sum(new_cs)
    float part = 0.0f;
#pragma unroll
    for (int i = 0; i < 4; i++) {
        int k = tid + i * 256;
        part += ema_cs[k] * DECAYF + g_counts[k] * OMDF;
    }
    sred[tid] = part;
    __syncthreads();
    for (int s = 128; s > 0; s >>= 1) {
        if (tid < s) sred[tid] += sred[tid + s];
        __syncthreads();
    }
    float n = sred[0];

    int lane = tid & 15;
#pragma unroll 1
    for (int g = 0; g < 4; g++) {
        int k2 = blockIdx.x * 64 + g * 16 + (tid >> 4);
        float cs = ema_cs[k2] * DECAYF + g_counts[k2] * OMDF;
        float cluster = (cs + EPSV) / (n + KK * EPSV) * n;
        float inv = 1.0f / fmaxf(cluster, EPSV);
        float4 w = *(const float4*)(ema_w + (size_t)k2 * 64 + lane * 4);
        float4 dv = *(const float4*)(g_dw + (size_t)k2 * 64 + lane * 4);
        float4 m;
        m.x = (w.x * DECAYF + dv.x * OMDF) * inv;
        m.y = (w.y * DECAYF + dv.y * OMDF) * inv;
        m.z = (w.z * DECAYF + dv.z * OMDF) * inv;
        m.w = (w.w * DECAYF + dv.w * OMDF) * inv;
        float ss = group16sum(m.x * m.x + m.y * m.y + m.z * m.z + m.w * m.w);
        float ni = 1.0f / fmaxf(sqrtf(ss), EPSV);
        *(float4*)(g_embed_unit + (size_t)k2 * 64 + lane * 4) =
            make_float4(m.x * ni, m.y * ni, m.z * ni, m.w * ni);
    }
}

// ---------------- kernel 5: gather + outputs ----------------
__global__ void k_out(const float* __restrict__ ze, float* __restrict__ out, int write_aux) {
    int w = (blockIdx.x * blockDim.x + threadIdx.x) >> 5;
    int lane = threadIdx.x & 31;
    if (w >= BB) return;
    int c = g_codes[w];
    float zl = g_znorm[w];
    float zinv = 1.0f / zl;
    float2 e = *(const float2*)(g_embed_unit + (size_t)c * 64 + lane * 2);
    float ss = warpsum(e.x * e.x + e.y * e.y);
    float ed = fmaxf(sqrtf(ss), EPSV);
    float2 en = make_float2(e.x / ed, e.y / ed);
    float2 zev = *(const float2*)(ze + (size_t)w * 64 + lane * 2);
    float2 zn = make_float2(zev.x * zinv, zev.y * zinv);
    float dot = warpsum(zn.x * en.x + zn.y * en.y);
    float2 zq = make_float2(e.x * zl, e.y * zl);
    float2 o = make_float2(zev.x + (zq.x - zev.x), zev.y + (zq.y - zev.y));
    *(float2*)(out + (size_t)w * 64 + lane * 2) = o;
    if (write_aux && lane == 0) {
        out[(size_t)BB * DD + w] = (float)c;
        out[(size_t)BB * DD + BB + w] = 1.0f - dot;
    }
}

// ---------------- launcher ----------------
extern "C" void kernel_launch(void* const* d_in, const int* in_sizes, int n_in,
                              void* d_out, int out_size) {
    const float* ze  = (const float*)d_in[0];
    const float* emb = (const float*)d_in[1];
    const float* ecs = (const float*)d_in[2];
    const float* ew  = (const float*)d_in[3];
    float* out = (float*)d_out;

    long long need = (long long)BB * DD + 2LL * BB;
    int write_aux = ((long long)out_size >= need) ? 1 : 0;

    cudaFuncSetAttribute(k_sim, cudaFuncAttributeMaxDynamicSharedMemorySize, SMEM_BYTES);

    k_prep<<<ZERO_BLOCKS + KK / 8, 256>>>(emb);
    k_sim<<<BB / 128, 256, SMEM_BYTES>>>(ze);
    k_rescore<<<BB / 8, 256>>>(ze);
    k_ema<<<16, 256>>>(ecs, ew);
    k_out<<<BB / 8, 256>>>(ze, out, write_aux);
}